// round 4
// baseline (speedup 1.0000x reference)
#include <cuda_runtime.h>
#include <cuda_bf16.h>

#define NSTEP 365
#define NGRID 50000
#define PRECS_F 1e-5f
#define PF 5   // prefetch depth; 365 = 5 * 73 exactly

__global__ __launch_bounds__(256, 4)
void hbv_kernel(const float* __restrict__ x,
                const float* __restrict__ params,
                float* __restrict__ out)
{
    const int g = blockIdx.x * blockDim.x + threadIdx.x;
    if (g >= NGRID) return;

    // ---- load & scale the 12 parameters (read once, L2-cached fine) ----
    const float* pp = params + (size_t)g * 14;
    float raw[12];
#pragma unroll
    for (int i = 0; i < 12; i++) raw[i] = pp[i];

    const float BETA  = 1.0f   + raw[0]  * 5.0f;     // [1, 6]
    const float FC    = 50.0f  + raw[1]  * 950.0f;   // [50, 1000]
    const float K0    = 0.05f  + raw[2]  * 0.85f;    // [0.05, 0.9]
    const float K1    = 0.01f  + raw[3]  * 0.49f;    // [0.01, 0.5]
    const float K2    = 0.001f + raw[4]  * 0.199f;   // [0.001, 0.2]
    const float LP    = 0.2f   + raw[5]  * 0.8f;     // [0.2, 1]
    const float PERCp =          raw[6]  * 10.0f;    // [0, 10]
    const float UZL   =          raw[7]  * 100.0f;   // [0, 100]
    const float TT    = -2.5f  + raw[8]  * 5.0f;     // [-2.5, 2.5]
    const float CFMAX = 0.5f   + raw[9]  * 9.5f;     // [0.5, 10]
    const float CFR   =          raw[10] * 0.1f;     // [0, 0.1]
    const float CWH   =          raw[11] * 0.2f;     // [0, 0.2]

    const float CFRC    = CFR * CFMAX;
    const float invFC   = 1.0f / FC;
    const float invLPFC = 1.0f / (LP * FC);

    // ---- state ----
    float SNOWPACK = 1e-3f, MELTWATER = 1e-3f, SM = 1e-3f, SUZ = 1e-3f, SLZ = 1e-3f;

    // ---- depth-PF register prefetch ring for x (decouples LDG from recurrence) ----
    const float* xp = x + (size_t)g * 3;
    const size_t  tstride = (size_t)NGRID * 3;

    float bP[PF], bT[PF], bE[PF];
#pragma unroll
    for (int i = 0; i < PF; i++) {
        const float* q = xp + (size_t)i * tstride;
        bP[i] = __ldcs(q);
        bT[i] = __ldcs(q + 1);
        bE[i] = __ldcs(q + 2);
    }

    float* op = out + g;

#pragma unroll 1
    for (int t0 = 0; t0 < NSTEP; t0 += PF) {
#pragma unroll
        for (int i = 0; i < PF; i++) {
            const int t = t0 + i;

            const float P = bP[i];
            const float T = bT[i];
            const float E = bE[i];

            // prefetch step t+PF (address independent of state -> overlaps compute)
            const int tn = t + PF;
            if (tn < NSTEP) {
                const float* q = xp + (size_t)tn * tstride;
                bP[i] = __ldcs(q);
                bT[i] = __ldcs(q + 1);
                bE[i] = __ldcs(q + 2);
            }

            // ---- snow routine ----
            const bool  rain = (T >= TT);
            const float RAIN = rain ? P : 0.0f;
            const float SNOW = rain ? 0.0f : P;
            SNOWPACK += SNOW;

            const float melt = fminf(fmaxf(CFMAX * (T - TT), 0.0f), SNOWPACK);
            MELTWATER += melt;
            SNOWPACK  -= melt;

            const float refr = fminf(fmaxf(CFRC * (TT - T), 0.0f), MELTWATER);
            SNOWPACK  += refr;
            MELTWATER -= refr;

            const float tosoil = fmaxf(MELTWATER - CWH * SNOWPACK, 0.0f);
            MELTWATER -= tosoil;

            // ---- soil routine ----
            const float r  = SM * invFC;                    // in (0, 1]
            const float sw = __saturatef(__powf(r, BETA));  // clip((SM/FC)^beta, 0, 1)

            const float rt       = RAIN + tosoil;
            const float recharge = rt * sw;
            SM += rt - recharge;

            const float excess = fmaxf(SM - FC, 0.0f);
            SM -= excess;

            const float evapf = __saturatef(SM * invLPFC);
            const float ETact = fminf(SM, E * evapf);
            SM = fmaxf(SM - ETact, PRECS_F);

            // ---- response routine ----
            SUZ += recharge + excess;
            const float PERC = fminf(SUZ, PERCp);
            SUZ -= PERC;
            const float Q0 = K0 * fmaxf(SUZ - UZL, 0.0f);
            SUZ -= Q0;
            const float Q1 = K1 * SUZ;
            SUZ -= Q1;
            SLZ += PERC;
            const float Q2 = K2 * SLZ;
            SLZ -= Q2;

            __stcs(op + (size_t)t * NGRID, Q0 + Q1 + Q2);
        }
    }
}

extern "C" void kernel_launch(void* const* d_in, const int* in_sizes, int n_in,
                              void* d_out, int out_size)
{
    const float* x      = (const float*)d_in[0];   // (365, 50000, 3)
    const float* params = (const float*)d_in[1];   // (50000, 14)
    float* out = (float*)d_out;                    // (365, 50000, 1)

    const int threads = 256;
    const int blocks  = (NGRID + threads - 1) / threads;
    hbv_kernel<<<blocks, threads>>>(x, params, out);
}